// round 11
// baseline (speedup 1.0000x reference)
#include <cuda_runtime.h>
#include <math.h>
#include <stdint.h>

// ---------------------------------------------------------------------------
// Problem constants
// ---------------------------------------------------------------------------
namespace {
constexpr int BATCH = 32;
constexpr int HH    = 56;
constexpr int WWd   = 56;
constexpr int C     = 512;
constexpr int NH    = 16;
constexpr int WS    = 7;
constexpr int SSH   = 3;                 // shift size
constexpr int HD    = C / NH;            // 32
constexpr int NT    = WS * WS;           // 49 tokens per window
constexpr int NWIN  = (HH / WS) * (WWd / WS);  // 64 windows per image
constexpr int GWIN  = BATCH * NWIN;      // 2048 windows total
constexpr int M     = GWIN * NT;         // 100352 rows
constexpr float SCALE = 0.17677669529663687f;  // HD^-0.5
constexpr float EPS   = 1e-5f;
constexpr int RB0 = HH - WS;  // 49
constexpr int RB1 = HH - SSH; // 53
}

// ---------------------------------------------------------------------------
// Scratch (device globals: allocation-free rule)
// ---------------------------------------------------------------------------
__device__ __align__(16) float g_xw  [(size_t)M * C];
__device__ __align__(16) float g_q   [(size_t)GWIN * NH * NT * HD];
__device__ __align__(16) float g_k   [(size_t)GWIN * NH * NT * HD];
__device__ __align__(16) float g_v   [(size_t)GWIN * NH * NT * HD];
__device__ __align__(16) float g_o   [(size_t)M * C];
__device__ __align__(16) float g_xres[(size_t)M * C];
__device__ __align__(16) float g_h1  [(size_t)M * 4 * C];

// ---------------------------------------------------------------------------
// LayerNorm (one row per block, 256 threads)
// ---------------------------------------------------------------------------
template<bool SHIFT>
__global__ void __launch_bounds__(256) ln_kernel(const float* __restrict__ src,
                                                 const float* __restrict__ w,
                                                 const float* __restrict__ b,
                                                 float* __restrict__ dst)
{
    int row = blockIdx.x;
    const float* sp;
    if (SHIFT) {
        int win = row / NT, tok = row - win * NT;
        int bi = win >> 6, wi = (win >> 3) & 7, wj = win & 7;
        int yi = tok / WS, xi = tok - yi * WS;
        int h0 = (wi * WS + yi + SSH) % HH;
        int w0 = (wj * WS + xi + SSH) % WWd;
        sp = src + ((size_t)bi * (HH * WWd) + h0 * WWd + w0) * C;
    } else {
        sp = src + (size_t)row * C;
    }
    int t = threadIdx.x;
    float v0 = sp[t], v1 = sp[t + 256];
    float s = v0 + v1, s2 = v0 * v0 + v1 * v1;
#pragma unroll
    for (int o = 16; o; o >>= 1) {
        s  += __shfl_xor_sync(0xffffffffu, s,  o);
        s2 += __shfl_xor_sync(0xffffffffu, s2, o);
    }
    __shared__ float red[16];
    if ((t & 31) == 0) { red[t >> 5] = s; red[(t >> 5) + 8] = s2; }
    __syncthreads();
    float S = 0.f, S2 = 0.f;
#pragma unroll
    for (int i = 0; i < 8; i++) { S += red[i]; S2 += red[i + 8]; }
    float mean = S * (1.0f / C);
    float var  = S2 * (1.0f / C) - mean * mean;
    float r = rsqrtf(var + EPS);
    float* dp = dst + (size_t)row * C;
    dp[t]       = (v0 - mean) * r * w[t]       + b[t];
    dp[t + 256] = (v1 - mean) * r * w[t + 256] + b[t + 256];
}

// ---------------------------------------------------------------------------
// TF32 tensor-core GEMM:  Cmat[m][n] = sum_k A[m][k] * Bw[n][k]  (+ epilogue)
// 128x128 CTA tile, BK=16, 256 threads, warp tile 64x32 via m16n8k8 mma.
// Tiles are staged into smem in FRAGMENT ORDER:
//   A:  As[buf][kstep][mfrag(8)][128 floats] ; thread reads its 4 A regs as
//       one LDS.128 at a 16B-granule XOR-swizzled lane index.
//   B:  Bs[buf][kstep][nfrag(16)][72 floats]; thread reads 2 B regs as LDS.64.
// ---------------------------------------------------------------------------
__device__ __forceinline__ float to_tf32(float x) {
    uint32_t u; asm("cvt.rna.tf32.f32 %0, %1;" : "=r"(u) : "f"(x));
    return __uint_as_float(u);
}

template<int EPI, int K>
__global__ void __launch_bounds__(256, 2) gemm_tf32(
    const float* __restrict__ A, const float* __restrict__ Bw,
    const float* __restrict__ bias,
    const float* __restrict__ extra,
    float* __restrict__ out0, float* __restrict__ out1, float* __restrict__ out2)
{
    __shared__ __align__(16) float As[2][2][8][128];   // 16 KB
    __shared__ __align__(16) float Bs[2][2][16][72];   // 18 KB

    const int m0 = blockIdx.y * 128;
    const int n0 = blockIdx.x * 128;
    const int t    = threadIdx.x;
    const int warp = t >> 5, lane = t & 31;
    const int wm = warp >> 2, wn = warp & 3;     // warp grid 2 x 4
    const int g  = lane >> 2, tg = lane & 3;     // mma quad layout
    const int rl = lane ^ ((lane >> 2) & 3);     // swizzled A read lane

    // staging assignment: thread -> (row in tile, k-step)
    const int srow = t >> 1;                     // 0..127
    const int sks  = t & 1;                      // 0..1
    const float* Ag = A  + (size_t)(m0 + srow) * K + sks * 8;
    const float* Bg = Bw + (size_t)(n0 + srow) * K + sks * 8;
    const int a_mf = srow >> 4, a_m8 = (srow >> 3) & 1, a_g = srow & 7;
    const int b_nf = srow >> 3,                  b_g = srow & 7;
    int aw[4];
#pragma unroll
    for (int q = 0; q < 4; q++)
        aw[q] = (((a_g * 4 + q) ^ (a_g & 3)) << 2) + a_m8;

    float acc[4][4][4];
#pragma unroll
    for (int i = 0; i < 4; i++)
#pragma unroll
        for (int j = 0; j < 4; j++)
#pragma unroll
            for (int c = 0; c < 4; c++) acc[i][j][c] = 0.f;

    constexpr int ITERS = K / 16;

    float4 av0, av1, bv0, bv1;
    av0 = *(const float4*)(Ag);
    av1 = *(const float4*)(Ag + 4);
    bv0 = *(const float4*)(Bg);
    bv1 = *(const float4*)(Bg + 4);

    auto stage = [&](int buf) {
        float* ap = &As[buf][sks][a_mf][0];
        ap[aw[0]]     = to_tf32(av0.x);
        ap[aw[1]]     = to_tf32(av0.y);
        ap[aw[2]]     = to_tf32(av0.z);
        ap[aw[3]]     = to_tf32(av0.w);
        ap[aw[0] + 2] = to_tf32(av1.x);
        ap[aw[1] + 2] = to_tf32(av1.y);
        ap[aw[2] + 2] = to_tf32(av1.z);
        ap[aw[3] + 2] = to_tf32(av1.w);
        float* bp = &Bs[buf][sks][b_nf][b_g * 8];
        float4 w0 = make_float4(to_tf32(bv0.x), to_tf32(bv1.x),
                                to_tf32(bv0.y), to_tf32(bv1.y));
        float4 w1 = make_float4(to_tf32(bv0.z), to_tf32(bv1.z),
                                to_tf32(bv0.w), to_tf32(bv1.w));
        *(float4*)bp       = w0;
        *(float4*)(bp + 4) = w1;
    };

    stage(0);
    __syncthreads();

    for (int it = 0; it < ITERS; ++it) {
        const int buf = it & 1;
        if (it + 1 < ITERS) {
            const float* ag = Ag + (it + 1) * 16;
            const float* bg = Bg + (it + 1) * 16;
            av0 = *(const float4*)ag;       av1 = *(const float4*)(ag + 4);
            bv0 = *(const float4*)bg;       bv1 = *(const float4*)(bg + 4);
        }
#pragma unroll
        for (int ks = 0; ks < 2; ks++) {
            uint32_t af[4][4];
            uint32_t bf[4][2];
#pragma unroll
            for (int mf = 0; mf < 4; mf++) {
                float4 v = *(const float4*)&As[buf][ks][wm * 4 + mf][rl * 4];
                af[mf][0] = __float_as_uint(v.x);
                af[mf][1] = __float_as_uint(v.y);
                af[mf][2] = __float_as_uint(v.z);
                af[mf][3] = __float_as_uint(v.w);
            }
#pragma unroll
            for (int nf = 0; nf < 4; nf++) {
                float2 v = *(const float2*)&Bs[buf][ks][wn * 4 + nf][lane * 2];
                bf[nf][0] = __float_as_uint(v.x);
                bf[nf][1] = __float_as_uint(v.y);
            }
#pragma unroll
            for (int mf = 0; mf < 4; mf++)
#pragma unroll
                for (int nf = 0; nf < 4; nf++)
                    asm volatile(
                        "mma.sync.aligned.m16n8k8.row.col.f32.tf32.tf32.f32 "
                        "{%0,%1,%2,%3}, {%4,%5,%6,%7}, {%8,%9}, {%0,%1,%2,%3};\n"
                        : "+f"(acc[mf][nf][0]), "+f"(acc[mf][nf][1]),
                          "+f"(acc[mf][nf][2]), "+f"(acc[mf][nf][3])
                        : "r"(af[mf][0]), "r"(af[mf][1]),
                          "r"(af[mf][2]), "r"(af[mf][3]),
                          "r"(bf[nf][0]), "r"(bf[nf][1]));
        }
        if (it + 1 < ITERS) {
            stage((it + 1) & 1);
            __syncthreads();
        }
    }

    // epilogue
#pragma unroll
    for (int mf = 0; mf < 4; mf++)
#pragma unroll
    for (int nf = 0; nf < 4; nf++)
#pragma unroll
    for (int cr = 0; cr < 4; cr++) {
        int m = m0 + wm * 64 + mf * 16 + g + ((cr >> 1) << 3);
        int n = n0 + wn * 32 + nf * 8 + tg * 2 + (cr & 1);
        float val = acc[mf][nf][cr] + bias[n];
        if (EPI == 0) {
            int which = n >> 9, cc = n & 511;
            int head = cc >> 5, d = cc & 31;
            int win = m / NT, tok = m - win * NT;
            size_t idx = (((size_t)win * NH + head) * NT + tok) * HD + d;
            if (which == 0)      out0[idx] = val * SCALE;
            else if (which == 1) out1[idx] = val;
            else                 out2[idx] = val;
        } else if (EPI == 1) {
            int win = m / NT, tok = m - win * NT;
            int bi = win >> 6, wi = (win >> 3) & 7, wj = win & 7;
            int yi = tok / WS, xi = tok - yi * WS;
            int h0 = (wi * WS + yi + SSH) % HH;
            int w0 = (wj * WS + xi + SSH) % WWd;
            size_t idx = ((size_t)bi * (HH * WWd) + h0 * WWd + w0) * C + n;
            out0[idx] = extra[idx] + val;
        } else if (EPI == 2) {
            float gl = 0.5f * val * (1.0f + erff(val * 0.70710678118654752f));
            out0[(size_t)m * (4 * C) + n] = gl;
        } else {
            size_t idx = (size_t)m * C + n;
            out0[idx] = extra[idx] + val;
        }
    }
}

// ---------------------------------------------------------------------------
// Windowed attention: one block per (window, head). 128 threads.
// ---------------------------------------------------------------------------
__global__ void __launch_bounds__(128) attn_kernel(
    const float* __restrict__ q, const float* __restrict__ k,
    const float* __restrict__ v, const float* __restrict__ rp,
    float* __restrict__ o)
{
    int wh = blockIdx.x;
    int win = wh >> 4, head = wh & 15;

    __shared__ float Qs[NT][HD], Ks[NT][HD], Vs[NT][HD];
    __shared__ float S[NT][NT];

    const size_t base = (size_t)wh * NT * HD;
    int t = threadIdx.x;
    for (int i = t; i < NT * HD; i += 128) {
        Qs[i / HD][i % HD] = q[base + i];
        Ks[i / HD][i % HD] = k[base + i];
        Vs[i / HD][i % HD] = v[base + i];
    }
    __syncthreads();

    int wi = (win >> 3) & 7, wj = win & 7;
    for (int idx = t; idx < NT * NT; idx += 128) {
        int r = idx / NT, c = idx - r * NT;
        float s = 0.f;
#pragma unroll
        for (int d = 0; d < HD; d++) s = fmaf(Qs[r][d], Ks[c][d], s);
        int yr = r / WS, xr = r - yr * WS;
        int yc = c / WS, xc = c - yc * WS;
        s += rp[((yr - yc + WS - 1) * (2 * WS - 1) + (xr - xc + WS - 1)) * NH + head];
        int hr = wi * WS + yr, wr = wj * WS + xr;
        int hc = wi * WS + yc, wc = wj * WS + xc;
        int ra = (hr < RB0 ? 0 : (hr < RB1 ? 1 : 2)) * 3 + (wr < RB0 ? 0 : (wr < RB1 ? 1 : 2));
        int rb = (hc < RB0 ? 0 : (hc < RB1 ? 1 : 2)) * 3 + (wc < RB0 ? 0 : (wc < RB1 ? 1 : 2));
        if (ra != rb) s -= 100.0f;
        S[r][c] = s;
    }
    __syncthreads();

    int warp = t >> 5, lane = t & 31;
    for (int r = warp; r < NT; r += 4) {
        float mx = -1e30f;
        for (int c = lane; c < NT; c += 32) mx = fmaxf(mx, S[r][c]);
#pragma unroll
        for (int off = 16; off; off >>= 1) mx = fmaxf(mx, __shfl_xor_sync(0xffffffffu, mx, off));
        float sum = 0.f;
        for (int c = lane; c < NT; c += 32) {
            float e = __expf(S[r][c] - mx);
            S[r][c] = e;
            sum += e;
        }
#pragma unroll
        for (int off = 16; off; off >>= 1) sum += __shfl_xor_sync(0xffffffffu, sum, off);
        float inv = 1.0f / sum;
        for (int c = lane; c < NT; c += 32) S[r][c] *= inv;
    }
    __syncthreads();

    for (int idx = t; idx < NT * HD; idx += 128) {
        int r = idx >> 5, d = idx & 31;
        float s = 0.f;
#pragma unroll
        for (int c = 0; c < NT; c++) s = fmaf(S[r][c], Vs[c][d], s);
        o[((size_t)win * NT + r) * C + head * HD + d] = s;
    }
}

// ---------------------------------------------------------------------------
// Launch
// ---------------------------------------------------------------------------
extern "C" void kernel_launch(void* const* d_in, const int* in_sizes, int n_in,
                              void* d_out, int out_size)
{
    (void)in_sizes; (void)n_in; (void)out_size;
    const float* x     = (const float*)d_in[0];
    const float* n1w   = (const float*)d_in[1];
    const float* n1b   = (const float*)d_in[2];
    const float* qkv_w = (const float*)d_in[3];
    const float* qkv_b = (const float*)d_in[4];
    const float* rp    = (const float*)d_in[5];
    const float* out_w = (const float*)d_in[6];
    const float* out_b = (const float*)d_in[7];
    const float* n2w   = (const float*)d_in[8];
    const float* n2b   = (const float*)d_in[9];
    const float* fc1_w = (const float*)d_in[10];
    const float* fc1_b = (const float*)d_in[11];
    const float* fc2_w = (const float*)d_in[12];
    const float* fc2_b = (const float*)d_in[13];
    float* out = (float*)d_out;

    float *xw, *q, *k, *v, *o, *xres, *h1;
    cudaGetSymbolAddress((void**)&xw,   g_xw);
    cudaGetSymbolAddress((void**)&q,    g_q);
    cudaGetSymbolAddress((void**)&k,    g_k);
    cudaGetSymbolAddress((void**)&v,    g_v);
    cudaGetSymbolAddress((void**)&o,    g_o);
    cudaGetSymbolAddress((void**)&xres, g_xres);
    cudaGetSymbolAddress((void**)&h1,   g_h1);

    const int MT = M / 128;  // 784 m-tiles

    // 1. LN1 + shift + window partition
    ln_kernel<true><<<M, 256>>>(x, n1w, n1b, xw);
    // 2. qkv GEMM -> Q/K/V (head-major)
    gemm_tf32<0, 512><<<dim3(12, MT), 256>>>(xw, qkv_w, qkv_b, nullptr, q, k, v);
    // 3. windowed attention
    attn_kernel<<<GWIN * NH, 128>>>(q, k, v, rp, o);
    // 4. output projection + window reverse + unshift + residual
    gemm_tf32<1, 512><<<dim3(4, MT), 256>>>(o, out_w, out_b, x, xres, nullptr, nullptr);
    // 5. LN2
    ln_kernel<false><<<M, 256>>>(xres, n2w, n2b, xw);
    // 6. fc1 + GELU
    gemm_tf32<2, 512><<<dim3(16, MT), 256>>>(xw, fc1_w, fc1_b, nullptr, h1, nullptr, nullptr);
    // 7. fc2 + residual -> out
    gemm_tf32<3, 2048><<<dim3(4, MT), 256>>>(h1, fc2_w, fc2_b, xres, out, nullptr, nullptr);
}

// round 16
// speedup vs baseline: 2.2662x; 2.2662x over previous
#include <cuda_runtime.h>
#include <cuda_fp16.h>
#include <math.h>
#include <stdint.h>

// ---------------------------------------------------------------------------
// Problem constants
// ---------------------------------------------------------------------------
namespace {
constexpr int BATCH = 32;
constexpr int HH    = 56;
constexpr int WWd   = 56;
constexpr int C     = 512;
constexpr int NH    = 16;
constexpr int WS    = 7;
constexpr int SSH   = 3;
constexpr int HD    = C / NH;            // 32
constexpr int NT    = WS * WS;           // 49
constexpr int NWIN  = (HH / WS) * (WWd / WS);
constexpr int GWIN  = BATCH * NWIN;      // 2048
constexpr int M     = GWIN * NT;         // 100352
constexpr float SCALE = 0.17677669529663687f;
constexpr float EPS   = 1e-5f;
constexpr int RB0 = HH - WS;   // 49
constexpr int RB1 = HH - SSH;  // 53

// fp16 mma GEMM tiling
constexpr int BM = 256, BN = 128, BK = 32;         // BK halves = 64B rows
constexpr int STAGES = 5;
constexpr int A_BYTES = BM * BK * 2;               // 16384
constexpr int B_BYTES = BN * BK * 2;               // 8192
constexpr int STAGE_BYTES = A_BYTES + B_BYTES;     // 24576
constexpr int SMEM_BYTES  = STAGES * STAGE_BYTES + 1024;

// weight scratch offsets (halves)
constexpr size_t W_QKV = 0;
constexpr size_t W_OUT = (size_t)3 * C * C;
constexpr size_t W_FC1 = W_OUT + (size_t)C * C;
constexpr size_t W_FC2 = W_FC1 + (size_t)4 * C * C;
constexpr size_t W_TOT = W_FC2 + (size_t)4 * C * C;
}

// ---------------------------------------------------------------------------
// Scratch (device globals: allocation-free rule)
// ---------------------------------------------------------------------------
__device__ __align__(16) __half g_xw  [(size_t)M * C];            // LN1/LN2 out (fp16)
__device__ __align__(16) float  g_q   [(size_t)GWIN * NH * NT * HD];
__device__ __align__(16) float  g_k   [(size_t)GWIN * NH * NT * HD];
__device__ __align__(16) float  g_v   [(size_t)GWIN * NH * NT * HD];
__device__ __align__(16) __half g_o   [(size_t)M * C];            // attn out (fp16)
__device__ __align__(16) float  g_xres[(size_t)M * C];
__device__ __align__(16) __half g_h1  [(size_t)M * 4 * C];        // gelu out (fp16)
__device__ __align__(16) __half g_wt  [W_TOT];

// ---------------------------------------------------------------------------
// PTX helpers
// ---------------------------------------------------------------------------
__device__ __forceinline__ uint32_t smem_u32(const void* p) {
    uint32_t a;
    asm("{ .reg .u64 t; cvta.to.shared.u64 t, %1; cvt.u32.u64 %0, t; }"
        : "=r"(a) : "l"(p));
    return a;
}
__device__ __forceinline__ void cp16(uint32_t dst, const void* src) {
    asm volatile("cp.async.cg.shared.global [%0], [%1], 16;"
                 :: "r"(dst), "l"(src) : "memory");
}
__device__ __forceinline__ void ldsm4(uint32_t* r, uint32_t addr) {
    asm volatile("ldmatrix.sync.aligned.m8n8.x4.shared.b16 {%0,%1,%2,%3}, [%4];"
                 : "=r"(r[0]), "=r"(r[1]), "=r"(r[2]), "=r"(r[3]) : "r"(addr));
}
__device__ __forceinline__ void mma_f16(float* d, const uint32_t* a, const uint32_t* b) {
    asm volatile(
        "mma.sync.aligned.m16n8k16.row.col.f32.f16.f16.f32 "
        "{%0,%1,%2,%3}, {%4,%5,%6,%7}, {%8,%9}, {%0,%1,%2,%3};"
        : "+f"(d[0]), "+f"(d[1]), "+f"(d[2]), "+f"(d[3])
        : "r"(a[0]), "r"(a[1]), "r"(a[2]), "r"(a[3]), "r"(b[0]), "r"(b[1]));
}

// ---------------------------------------------------------------------------
// Weight fp16 conversion
// ---------------------------------------------------------------------------
__global__ void __launch_bounds__(256) cvt_h(const float4* __restrict__ s,
                                             __half2* __restrict__ d, int n4)
{
    int i = blockIdx.x * 256 + threadIdx.x;
    if (i < n4) {
        float4 v = s[i];
        d[2 * i]     = __floats2half2_rn(v.x, v.y);
        d[2 * i + 1] = __floats2half2_rn(v.z, v.w);
    }
}

// ---------------------------------------------------------------------------
// LayerNorm -> fp16 (it always feeds a GEMM A operand)
// ---------------------------------------------------------------------------
template<bool SHIFT>
__global__ void __launch_bounds__(256) ln_kernel(const float* __restrict__ src,
                                                 const float* __restrict__ w,
                                                 const float* __restrict__ b,
                                                 __half* __restrict__ dst)
{
    int row = blockIdx.x;
    const float* sp;
    if (SHIFT) {
        int win = row / NT, tok = row - win * NT;
        int bi = win >> 6, wi = (win >> 3) & 7, wj = win & 7;
        int yi = tok / WS, xi = tok - yi * WS;
        int h0 = (wi * WS + yi + SSH) % HH;
        int w0 = (wj * WS + xi + SSH) % WWd;
        sp = src + ((size_t)bi * (HH * WWd) + h0 * WWd + w0) * C;
    } else {
        sp = src + (size_t)row * C;
    }
    int t = threadIdx.x;
    float v0 = sp[t], v1 = sp[t + 256];
    float s = v0 + v1, s2 = v0 * v0 + v1 * v1;
#pragma unroll
    for (int o = 16; o; o >>= 1) {
        s  += __shfl_xor_sync(0xffffffffu, s,  o);
        s2 += __shfl_xor_sync(0xffffffffu, s2, o);
    }
    __shared__ float red[16];
    if ((t & 31) == 0) { red[t >> 5] = s; red[(t >> 5) + 8] = s2; }
    __syncthreads();
    float S = 0.f, S2 = 0.f;
#pragma unroll
    for (int i = 0; i < 8; i++) { S += red[i]; S2 += red[i + 8]; }
    float mean = S * (1.0f / C);
    float var  = S2 * (1.0f / C) - mean * mean;
    float r = rsqrtf(var + EPS);
    __half* dp = dst + (size_t)row * C;
    dp[t]       = __float2half_rn((v0 - mean) * r * w[t]       + b[t]);
    dp[t + 256] = __float2half_rn((v1 - mean) * r * w[t + 256] + b[t + 256]);
}

// ---------------------------------------------------------------------------
// fp16 tensor-core GEMM: Cmat[m][n] = sum_k A[m][k]*Bw[n][k]  (+ epilogue)
// CTA 256x128, BK=32 halves, 8 warps (4x2), warp tile 64x64, m16n8k16 mma.
// 5-stage cp.async pipeline; smem 64B rows with 16B-chunk xor swizzle
// (chunk c -> c ^ ((row>>1)&3)) making both cp.async stores and ldmatrix
// reads bank-conflict-free.
// ---------------------------------------------------------------------------
template<int EPI, int K>
__global__ void __launch_bounds__(256, 1) gemm_f16(
    const __half* __restrict__ A, const __half* __restrict__ Bw,
    const float* __restrict__ bias,
    const float* __restrict__ extra,
    void* __restrict__ vout0, void* __restrict__ vout1, void* __restrict__ vout2)
{
    extern __shared__ char dsm[];
    const uint32_t base = (smem_u32(dsm) + 1023u) & ~1023u;

    const int t    = threadIdx.x;
    const int warp = t >> 5, lane = t & 31;
    const int wr = warp >> 1, wc = warp & 1;   // 4 x 2 warp grid

    const int m0 = blockIdx.y * BM;
    const int n0 = blockIdx.x * BN;
    const __half* Ag = A  + (size_t)m0 * K;
    const __half* Bg = Bw + (size_t)n0 * K;

    constexpr int ITERS = K / BK;

    float acc[4][8][4];
#pragma unroll
    for (int i = 0; i < 4; i++)
#pragma unroll
        for (int j = 0; j < 8; j++)
#pragma unroll
            for (int c = 0; c < 4; c++) acc[i][j][c] = 0.f;

    // stage tile it into buffer it % STAGES
    auto stg = [&](int it) {
        const int b = it % STAGES;
        const uint32_t sA = base + b * STAGE_BYTES;
        const uint32_t sB = sA + A_BYTES;
        const int k0 = it * BK;
#pragma unroll
        for (int q = 0; q < 4; q++) {           // A: 1024 16B chunks
            int ch = t + q * 256;
            int row = ch >> 2, ci = ch & 3;
            uint32_t off = row * 64 + ((ci ^ ((row >> 1) & 3)) << 4);
            cp16(sA + off, Ag + (size_t)row * K + k0 + ci * 8);
        }
#pragma unroll
        for (int q = 0; q < 2; q++) {           // B: 512 16B chunks
            int ch = t + q * 256;
            int row = ch >> 2, ci = ch & 3;
            uint32_t off = row * 64 + ((ci ^ ((row >> 1) & 3)) << 4);
            cp16(sB + off, Bg + (size_t)row * K + k0 + ci * 8);
        }
    };

#pragma unroll
    for (int s = 0; s < 4; s++) {
        stg(s);
        asm volatile("cp.async.commit_group;" ::: "memory");
    }

    for (int it = 0; it < ITERS; ++it) {
        asm volatile("cp.async.wait_group 3;" ::: "memory");
        __syncthreads();

        const int b = it % STAGES;
        const uint32_t sA = base + b * STAGE_BYTES;
        const uint32_t sB = sA + A_BYTES;
#pragma unroll
        for (int ks = 0; ks < 2; ks++) {
            uint32_t af[4][4];
#pragma unroll
            for (int mf = 0; mf < 4; mf++) {
                int mrow = wr * 64 + mf * 16 + (lane & 7) + ((lane >> 3) & 1) * 8;
                int kc = (ks * 2 + ((lane >> 4) & 1)) ^ ((mrow >> 1) & 3);
                ldsm4(af[mf], sA + mrow * 64 + kc * 16);
            }
            uint32_t bf[4][4];
#pragma unroll
            for (int p = 0; p < 4; p++) {
                int nrow = wc * 64 + p * 16 + (lane & 7) + ((lane >> 4) & 1) * 8;
                int kc = (ks * 2 + ((lane >> 3) & 1)) ^ ((nrow >> 1) & 3);
                ldsm4(bf[p], sB + nrow * 64 + kc * 16);
            }
#pragma unroll
            for (int mf = 0; mf < 4; mf++)
#pragma unroll
                for (int nf = 0; nf < 8; nf++) {
                    uint32_t bb[2] = { bf[nf >> 1][(nf & 1) * 2],
                                       bf[nf >> 1][(nf & 1) * 2 + 1] };
                    mma_f16(acc[mf][nf], af[mf], bb);
                }
        }

        if (it + 4 < ITERS) stg(it + 4);
        asm volatile("cp.async.commit_group;" ::: "memory");
    }

    // ---------------- epilogue ----------------
    float*  f0 = (float*)vout0;
    float*  f1 = (float*)vout1;
    float*  f2 = (float*)vout2;
    __half* h0 = (__half*)vout0;

#pragma unroll
    for (int mf = 0; mf < 4; mf++) {
#pragma unroll
        for (int h2 = 0; h2 < 2; h2++) {
            const int m = m0 + wr * 64 + mf * 16 + (lane >> 2) + h2 * 8;
            int win = 0, tok = 0;
            size_t rowbase = 0;
            if (EPI == 0 || EPI == 1) {
                win = m / NT; tok = m - win * NT;
                if (EPI == 1) {
                    int bi = win >> 6, wi = (win >> 3) & 7, wj = win & 7;
                    int yi = tok / WS, xi = tok - yi * WS;
                    int hh = (wi * WS + yi + SSH) % HH;
                    int ww = (wj * WS + xi + SSH) % WWd;
                    rowbase = ((size_t)bi * (HH * WWd) + hh * WWd + ww) * C;
                }
            }
#pragma unroll
            for (int nf = 0; nf < 8; nf++) {
#pragma unroll
                for (int c2 = 0; c2 < 2; c2++) {
                    const int n = n0 + wc * 64 + nf * 8 + (lane & 3) * 2 + c2;
                    float val = acc[mf][nf][h2 * 2 + c2] + bias[n];
                    if (EPI == 0) {
                        int which = n >> 9, cc = n & 511;
                        int head = cc >> 5, d = cc & 31;
                        size_t idx = (((size_t)win * NH + head) * NT + tok) * HD + d;
                        if (which == 0)      f0[idx] = val * SCALE;
                        else if (which == 1) f1[idx] = val;
                        else                 f2[idx] = val;
                    } else if (EPI == 1) {
                        size_t idx = rowbase + n;
                        f0[idx] = extra[idx] + val;
                    } else if (EPI == 2) {
                        float gl = 0.5f * val * (1.0f + erff(val * 0.70710678118654752f));
                        h0[(size_t)m * (4 * C) + n] = __float2half_rn(gl);
                    } else {
                        size_t idx = (size_t)m * C + n;
                        f0[idx] = extra[idx] + val;
                    }
                }
            }
        }
    }
}

// ---------------------------------------------------------------------------
// Windowed attention: one block per (window, head). 128 threads.
// Smem rows padded to HD+1 -> conflict-free strided lane access.
// ---------------------------------------------------------------------------
__global__ void __launch_bounds__(128) attn_kernel(
    const float* __restrict__ q, const float* __restrict__ k,
    const float* __restrict__ v, const float* __restrict__ rp,
    __half* __restrict__ o)
{
    int wh = blockIdx.x;
    int win = wh >> 4, head = wh & 15;

    __shared__ float Qs[NT][HD + 1], Ks[NT][HD + 1], Vs[NT][HD + 1];
    __shared__ float S[NT][NT];

    const size_t base = (size_t)wh * NT * HD;
    int t = threadIdx.x;
    for (int i = t; i < NT * HD; i += 128) {
        int r = i >> 5, d = i & 31;
        Qs[r][d] = q[base + i];
        Ks[r][d] = k[base + i];
        Vs[r][d] = v[base + i];
    }
    __syncthreads();

    int wi = (win >> 3) & 7, wj = win & 7;
    for (int idx = t; idx < NT * NT; idx += 128) {
        int r = idx / NT, c = idx - r * NT;
        float s = 0.f;
#pragma unroll
        for (int d = 0; d < HD; d++) s = fmaf(Qs[r][d], Ks[c][d], s);
        int yr = r / WS, xr = r - yr * WS;
        int yc = c / WS, xc = c - yc * WS;
        s += rp[((yr - yc + WS - 1) * (2 * WS - 1) + (xr - xc + WS - 1)) * NH + head];
        int hr = wi * WS + yr, wr = wj * WS + xr;
        int hc = wi * WS + yc, wc = wj * WS + xc;
        int ra = (hr < RB0 ? 0 : (hr < RB1 ? 1 : 2)) * 3 + (wr < RB0 ? 0 : (wr < RB1 ? 1 : 2));
        int rb = (hc < RB0 ? 0 : (hc < RB1 ? 1 : 2)) * 3 + (wc < RB0 ? 0 : (wc < RB1 ? 1 : 2));
        if (ra != rb) s -= 100.0f;
        S[r][c] = s;
    }
    __syncthreads();

    int warp = t >> 5, lane = t & 31;
    for (int r = warp; r < NT; r += 4) {
        float mx = -1e30f;
        for (int c = lane; c < NT; c += 32) mx = fmaxf(mx, S[r][c]);
#pragma unroll
        for (int off = 16; off; off >>= 1) mx = fmaxf(mx, __shfl_xor_sync(0xffffffffu, mx, off));
        float sum = 0.f;
        for (int c = lane; c < NT; c += 32) {
            float e = __expf(S[r][c] - mx);
            S[r][c] = e;
            sum += e;
        }
#pragma unroll
        for (int off = 16; off; off >>= 1) sum += __shfl_xor_sync(0xffffffffu, sum, off);
        float inv = 1.0f / sum;
        for (int c = lane; c < NT; c += 32) S[r][c] *= inv;
    }
    __syncthreads();

    for (int idx = t; idx < NT * HD; idx += 128) {
        int r = idx >> 5, d = idx & 31;
        float s = 0.f;
#pragma unroll
        for (int c = 0; c < NT; c++) s = fmaf(S[r][c], Vs[c][d], s);
        o[((size_t)win * NT + r) * C + head * HD + d] = __float2half_rn(s);
    }
}

// ---------------------------------------------------------------------------
// Launch
// ---------------------------------------------------------------------------
extern "C" void kernel_launch(void* const* d_in, const int* in_sizes, int n_in,
                              void* d_out, int out_size)
{
    (void)in_sizes; (void)n_in; (void)out_size;
    const float* x     = (const float*)d_in[0];
    const float* n1w   = (const float*)d_in[1];
    const float* n1b   = (const float*)d_in[2];
    const float* qkv_w = (const float*)d_in[3];
    const float* qkv_b = (const float*)d_in[4];
    const float* rp    = (const float*)d_in[5];
    const float* out_w = (const float*)d_in[6];
    const float* out_b = (const float*)d_in[7];
    const float* n2w   = (const float*)d_in[8];
    const float* n2b   = (const float*)d_in[9];
    const float* fc1_w = (const float*)d_in[10];
    const float* fc1_b = (const float*)d_in[11];
    const float* fc2_w = (const float*)d_in[12];
    const float* fc2_b = (const float*)d_in[13];
    float* out = (float*)d_out;

    __half *xw, *o, *h1, *wt;
    float *q, *k, *v, *xres;
    cudaGetSymbolAddress((void**)&xw,   g_xw);
    cudaGetSymbolAddress((void**)&q,    g_q);
    cudaGetSymbolAddress((void**)&k,    g_k);
    cudaGetSymbolAddress((void**)&v,    g_v);
    cudaGetSymbolAddress((void**)&o,    g_o);
    cudaGetSymbolAddress((void**)&xres, g_xres);
    cudaGetSymbolAddress((void**)&h1,   g_h1);
    cudaGetSymbolAddress((void**)&wt,   g_wt);

    cudaFuncSetAttribute(gemm_f16<0, 512>,  cudaFuncAttributeMaxDynamicSharedMemorySize, SMEM_BYTES);
    cudaFuncSetAttribute(gemm_f16<1, 512>,  cudaFuncAttributeMaxDynamicSharedMemorySize, SMEM_BYTES);
    cudaFuncSetAttribute(gemm_f16<2, 512>,  cudaFuncAttributeMaxDynamicSharedMemorySize, SMEM_BYTES);
    cudaFuncSetAttribute(gemm_f16<3, 2048>, cudaFuncAttributeMaxDynamicSharedMemorySize, SMEM_BYTES);

    const int MT = M / BM;  // 392 m-tiles

    // 0. weights -> fp16
    cvt_h<<<(3 * C * C / 4 + 255) / 256, 256>>>((const float4*)qkv_w, (__half2*)(wt + W_QKV), 3 * C * C / 4);
    cvt_h<<<(C * C / 4 + 255) / 256, 256>>>((const float4*)out_w, (__half2*)(wt + W_OUT), C * C / 4);
    cvt_h<<<(4 * C * C / 4 + 255) / 256, 256>>>((const float4*)fc1_w, (__half2*)(wt + W_FC1), 4 * C * C / 4);
    cvt_h<<<(4 * C * C / 4 + 255) / 256, 256>>>((const float4*)fc2_w, (__half2*)(wt + W_FC2), 4 * C * C / 4);

    // 1. LN1 + shift + window partition  (fp16 out)
    ln_kernel<true><<<M, 256>>>(x, n1w, n1b, xw);
    // 2. qkv GEMM -> Q/K/V (head-major, fp32)
    gemm_f16<0, 512><<<dim3(12, MT), 256, SMEM_BYTES>>>(xw, wt + W_QKV, qkv_b, nullptr, q, k, v);
    // 3. windowed attention (fp16 out)
    attn_kernel<<<GWIN * NH, 128>>>(q, k, v, rp, o);
    // 4. output projection + window reverse + unshift + residual (fp32)
    gemm_f16<1, 512><<<dim3(4, MT), 256, SMEM_BYTES>>>(o, wt + W_OUT, out_b, x, xres, nullptr, nullptr);
    // 5. LN2 (fp16 out)
    ln_kernel<false><<<M, 256>>>(xres, n2w, n2b, xw);
    // 6. fc1 + GELU (fp16 out)
    gemm_f16<2, 512><<<dim3(16, MT), 256, SMEM_BYTES>>>(xw, wt + W_FC1, fc1_b, nullptr, h1, nullptr, nullptr);
    // 7. fc2 + residual -> out (fp32)
    gemm_f16<3, 2048><<<dim3(4, MT), 256, SMEM_BYTES>>>(h1, wt + W_FC2, fc2_b, xres, out, nullptr, nullptr);
}

// round 17
// speedup vs baseline: 2.9930x; 1.3207x over previous
#include <cuda_runtime.h>
#include <cuda_fp16.h>
#include <math.h>
#include <stdint.h>

// ---------------------------------------------------------------------------
// Problem constants
// ---------------------------------------------------------------------------
namespace {
constexpr int BATCH = 32;
constexpr int HH    = 56;
constexpr int WWd   = 56;
constexpr int C     = 512;
constexpr int NH    = 16;
constexpr int WS    = 7;
constexpr int SSH   = 3;
constexpr int HD    = C / NH;            // 32
constexpr int NT    = WS * WS;           // 49
constexpr int NWIN  = (HH / WS) * (WWd / WS);
constexpr int GWIN  = BATCH * NWIN;      // 2048
constexpr int M     = GWIN * NT;         // 100352
constexpr float SCALE = 0.17677669529663687f;
constexpr float EPS   = 1e-5f;
constexpr int RB0 = HH - WS;   // 49
constexpr int RB1 = HH - SSH;  // 53

// fp16 mma GEMM tiling
constexpr int BM = 256, BN = 128, BK = 32;         // BK halves = 64B rows
constexpr int STAGES = 5;
constexpr int A_BYTES = BM * BK * 2;               // 16384
constexpr int B_BYTES = BN * BK * 2;               // 8192
constexpr int STAGE_BYTES = A_BYTES + B_BYTES;     // 24576
constexpr int SMEM_BYTES  = STAGES * STAGE_BYTES + 1024;

// weight scratch offsets (halves)
constexpr size_t W_QKV = 0;
constexpr size_t W_OUT = (size_t)3 * C * C;
constexpr size_t W_FC1 = W_OUT + (size_t)C * C;
constexpr size_t W_FC2 = W_FC1 + (size_t)4 * C * C;
constexpr size_t W_TOT = W_FC2 + (size_t)4 * C * C;
}

// ---------------------------------------------------------------------------
// Scratch (device globals: allocation-free rule)
// ---------------------------------------------------------------------------
__device__ __align__(16) __half g_xw  [(size_t)M * C];            // LN1/LN2 out (fp16)
__device__ __align__(16) __half g_q   [(size_t)GWIN * NH * NT * HD];
__device__ __align__(16) __half g_k   [(size_t)GWIN * NH * NT * HD];
__device__ __align__(16) __half g_v   [(size_t)GWIN * NH * NT * HD];
__device__ __align__(16) __half g_o   [(size_t)M * C];            // attn out (fp16)
__device__ __align__(16) float  g_xres[(size_t)M * C];
__device__ __align__(16) __half g_h1  [(size_t)M * 4 * C];        // gelu out (fp16)
__device__ __align__(16) __half g_wt  [W_TOT];

// ---------------------------------------------------------------------------
// PTX helpers
// ---------------------------------------------------------------------------
__device__ __forceinline__ uint32_t smem_u32(const void* p) {
    uint32_t a;
    asm("{ .reg .u64 t; cvta.to.shared.u64 t, %1; cvt.u32.u64 %0, t; }"
        : "=r"(a) : "l"(p));
    return a;
}
__device__ __forceinline__ void cp16(uint32_t dst, const void* src) {
    asm volatile("cp.async.cg.shared.global [%0], [%1], 16;"
                 :: "r"(dst), "l"(src) : "memory");
}
__device__ __forceinline__ void ldsm4(uint32_t* r, uint32_t addr) {
    asm volatile("ldmatrix.sync.aligned.m8n8.x4.shared.b16 {%0,%1,%2,%3}, [%4];"
                 : "=r"(r[0]), "=r"(r[1]), "=r"(r[2]), "=r"(r[3]) : "r"(addr));
}
__device__ __forceinline__ void ldsm4t(uint32_t* r, uint32_t addr) {
    asm volatile("ldmatrix.sync.aligned.m8n8.x4.trans.shared.b16 {%0,%1,%2,%3}, [%4];"
                 : "=r"(r[0]), "=r"(r[1]), "=r"(r[2]), "=r"(r[3]) : "r"(addr));
}
__device__ __forceinline__ void mma_f16(float* d, const uint32_t* a, const uint32_t* b) {
    asm volatile(
        "mma.sync.aligned.m16n8k16.row.col.f32.f16.f16.f32 "
        "{%0,%1,%2,%3}, {%4,%5,%6,%7}, {%8,%9}, {%0,%1,%2,%3};"
        : "+f"(d[0]), "+f"(d[1]), "+f"(d[2]), "+f"(d[3])
        : "r"(a[0]), "r"(a[1]), "r"(a[2]), "r"(a[3]), "r"(b[0]), "r"(b[1]));
}

// ---------------------------------------------------------------------------
// Weight fp16 conversion
// ---------------------------------------------------------------------------
__global__ void __launch_bounds__(256) cvt_h(const float4* __restrict__ s,
                                             __half2* __restrict__ d, int n4)
{
    int i = blockIdx.x * 256 + threadIdx.x;
    if (i < n4) {
        float4 v = s[i];
        d[2 * i]     = __floats2half2_rn(v.x, v.y);
        d[2 * i + 1] = __floats2half2_rn(v.z, v.w);
    }
}

// ---------------------------------------------------------------------------
// LayerNorm -> fp16 (it always feeds a GEMM A operand)
// ---------------------------------------------------------------------------
template<bool SHIFT>
__global__ void __launch_bounds__(256) ln_kernel(const float* __restrict__ src,
                                                 const float* __restrict__ w,
                                                 const float* __restrict__ b,
                                                 __half* __restrict__ dst)
{
    int row = blockIdx.x;
    const float* sp;
    if (SHIFT) {
        int win = row / NT, tok = row - win * NT;
        int bi = win >> 6, wi = (win >> 3) & 7, wj = win & 7;
        int yi = tok / WS, xi = tok - yi * WS;
        int h0 = (wi * WS + yi + SSH) % HH;
        int w0 = (wj * WS + xi + SSH) % WWd;
        sp = src + ((size_t)bi * (HH * WWd) + h0 * WWd + w0) * C;
    } else {
        sp = src + (size_t)row * C;
    }
    int t = threadIdx.x;
    float v0 = sp[t], v1 = sp[t + 256];
    float s = v0 + v1, s2 = v0 * v0 + v1 * v1;
#pragma unroll
    for (int o = 16; o; o >>= 1) {
        s  += __shfl_xor_sync(0xffffffffu, s,  o);
        s2 += __shfl_xor_sync(0xffffffffu, s2, o);
    }
    __shared__ float red[16];
    if ((t & 31) == 0) { red[t >> 5] = s; red[(t >> 5) + 8] = s2; }
    __syncthreads();
    float S = 0.f, S2 = 0.f;
#pragma unroll
    for (int i = 0; i < 8; i++) { S += red[i]; S2 += red[i + 8]; }
    float mean = S * (1.0f / C);
    float var  = S2 * (1.0f / C) - mean * mean;
    float r = rsqrtf(var + EPS);
    __half* dp = dst + (size_t)row * C;
    dp[t]       = __float2half_rn((v0 - mean) * r * w[t]       + b[t]);
    dp[t + 256] = __float2half_rn((v1 - mean) * r * w[t + 256] + b[t + 256]);
}

// ---------------------------------------------------------------------------
// fp16 tensor-core GEMM (unchanged mainloop from R16)
// ---------------------------------------------------------------------------
template<int EPI, int K>
__global__ void __launch_bounds__(256, 1) gemm_f16(
    const __half* __restrict__ A, const __half* __restrict__ Bw,
    const float* __restrict__ bias,
    const float* __restrict__ extra,
    void* __restrict__ vout0, void* __restrict__ vout1, void* __restrict__ vout2)
{
    extern __shared__ char dsm[];
    const uint32_t base = (smem_u32(dsm) + 1023u) & ~1023u;

    const int t    = threadIdx.x;
    const int warp = t >> 5, lane = t & 31;
    const int wr = warp >> 1, wc = warp & 1;   // 4 x 2 warp grid

    const int m0 = blockIdx.y * BM;
    const int n0 = blockIdx.x * BN;
    const __half* Ag = A  + (size_t)m0 * K;
    const __half* Bg = Bw + (size_t)n0 * K;

    constexpr int ITERS = K / BK;

    float acc[4][8][4];
#pragma unroll
    for (int i = 0; i < 4; i++)
#pragma unroll
        for (int j = 0; j < 8; j++)
#pragma unroll
            for (int c = 0; c < 4; c++) acc[i][j][c] = 0.f;

    auto stg = [&](int it) {
        const int b = it % STAGES;
        const uint32_t sA = base + b * STAGE_BYTES;
        const uint32_t sB = sA + A_BYTES;
        const int k0 = it * BK;
#pragma unroll
        for (int q = 0; q < 4; q++) {
            int ch = t + q * 256;
            int row = ch >> 2, ci = ch & 3;
            uint32_t off = row * 64 + ((ci ^ ((row >> 1) & 3)) << 4);
            cp16(sA + off, Ag + (size_t)row * K + k0 + ci * 8);
        }
#pragma unroll
        for (int q = 0; q < 2; q++) {
            int ch = t + q * 256;
            int row = ch >> 2, ci = ch & 3;
            uint32_t off = row * 64 + ((ci ^ ((row >> 1) & 3)) << 4);
            cp16(sB + off, Bg + (size_t)row * K + k0 + ci * 8);
        }
    };

#pragma unroll
    for (int s = 0; s < 4; s++) {
        stg(s);
        asm volatile("cp.async.commit_group;" ::: "memory");
    }

    for (int it = 0; it < ITERS; ++it) {
        asm volatile("cp.async.wait_group 3;" ::: "memory");
        __syncthreads();

        const int b = it % STAGES;
        const uint32_t sA = base + b * STAGE_BYTES;
        const uint32_t sB = sA + A_BYTES;
#pragma unroll
        for (int ks = 0; ks < 2; ks++) {
            uint32_t af[4][4];
#pragma unroll
            for (int mf = 0; mf < 4; mf++) {
                int mrow = wr * 64 + mf * 16 + (lane & 7) + ((lane >> 3) & 1) * 8;
                int kc = (ks * 2 + ((lane >> 4) & 1)) ^ ((mrow >> 1) & 3);
                ldsm4(af[mf], sA + mrow * 64 + kc * 16);
            }
            uint32_t bf[4][4];
#pragma unroll
            for (int p = 0; p < 4; p++) {
                int nrow = wc * 64 + p * 16 + (lane & 7) + ((lane >> 4) & 1) * 8;
                int kc = (ks * 2 + ((lane >> 3) & 1)) ^ ((nrow >> 1) & 3);
                ldsm4(bf[p], sB + nrow * 64 + kc * 16);
            }
#pragma unroll
            for (int mf = 0; mf < 4; mf++)
#pragma unroll
                for (int nf = 0; nf < 8; nf++) {
                    uint32_t bb[2] = { bf[nf >> 1][(nf & 1) * 2],
                                       bf[nf >> 1][(nf & 1) * 2 + 1] };
                    mma_f16(acc[mf][nf], af[mf], bb);
                }
        }

        if (it + 4 < ITERS) stg(it + 4);
        asm volatile("cp.async.commit_group;" ::: "memory");
    }

    // ---------------- epilogue ----------------
    float*  f0 = (float*)vout0;
    __half* hq = (__half*)vout0;
    __half* hk = (__half*)vout1;
    __half* hv = (__half*)vout2;
    __half* h0 = (__half*)vout0;

#pragma unroll
    for (int mf = 0; mf < 4; mf++) {
#pragma unroll
        for (int h2 = 0; h2 < 2; h2++) {
            const int m = m0 + wr * 64 + mf * 16 + (lane >> 2) + h2 * 8;
            int win = 0, tok = 0;
            size_t rowbase = 0;
            if (EPI == 0 || EPI == 1) {
                win = m / NT; tok = m - win * NT;
                if (EPI == 1) {
                    int bi = win >> 6, wi = (win >> 3) & 7, wj = win & 7;
                    int yi = tok / WS, xi = tok - yi * WS;
                    int hh = (wi * WS + yi + SSH) % HH;
                    int ww = (wj * WS + xi + SSH) % WWd;
                    rowbase = ((size_t)bi * (HH * WWd) + hh * WWd + ww) * C;
                }
            }
#pragma unroll
            for (int nf = 0; nf < 8; nf++) {
                const int n = n0 + wc * 64 + nf * 8 + (lane & 3) * 2;
                float v0 = acc[mf][nf][h2 * 2]     + bias[n];
                float v1 = acc[mf][nf][h2 * 2 + 1] + bias[n + 1];
                if (EPI == 0) {
                    int which = n >> 9, cc = n & 511;
                    int head = cc >> 5, d = cc & 31;
                    size_t idx = (((size_t)win * NH + head) * NT + tok) * HD + d;
                    __half* dst = (which == 0) ? hq : (which == 1) ? hk : hv;
                    float sc = (which == 0) ? SCALE : 1.0f;
                    *(__half2*)(dst + idx) = __floats2half2_rn(v0 * sc, v1 * sc);
                } else if (EPI == 1) {
                    size_t idx = rowbase + n;
                    f0[idx]     = extra[idx]     + v0;
                    f0[idx + 1] = extra[idx + 1] + v1;
                } else if (EPI == 2) {
                    float g0 = 0.5f * v0 * (1.0f + erff(v0 * 0.70710678118654752f));
                    float g1 = 0.5f * v1 * (1.0f + erff(v1 * 0.70710678118654752f));
                    *(__half2*)(h0 + (size_t)m * (4 * C) + n) = __floats2half2_rn(g0, g1);
                } else {
                    size_t idx = (size_t)m * C + n;
                    f0[idx]     = extra[idx]     + v0;
                    f0[idx + 1] = extra[idx + 1] + v1;
                }
            }
        }
    }
}

// ---------------------------------------------------------------------------
// Windowed attention with tensor cores. One block per (window, head),
// 128 threads / 4 warps. Warp w owns output rows [16w, 16w+16).
//   S = Q K^T + bias + mask  (m16n8k16, K as B-operand direct ldmatrix)
//   softmax fp32 in smem, P stored fp16 zero-padded to 64x64
//   O = P V                   (V^T fragments via ldmatrix.x4.trans)
// Q/K/V smem rows: 40 halves (80B) -> conflict-free ldmatrix phases.
// P smem rows: 72 halves (144B) -> conflict-free.
// ---------------------------------------------------------------------------
__global__ void __launch_bounds__(128) attn_mma(
    const __half* __restrict__ q, const __half* __restrict__ k,
    const __half* __restrict__ v, const float* __restrict__ rp,
    __half* __restrict__ o)
{
    int wh = blockIdx.x;
    int win = wh >> 4, head = wh & 15;

    __shared__ __align__(16) __half Qs[64 * 40], Ks[64 * 40], Vs[64 * 40];
    __shared__ __align__(16) float  Ss[64 * 64];
    __shared__ __align__(16) __half Ps[64 * 72];

    const int t = threadIdx.x, warp = t >> 5, lane = t & 31;
    const int g = lane >> 2, tg = lane & 3;

    // ---- load Q/K/V (49x32 halves each) + zero pads ----
    {
        const __half2* Q2 = (const __half2*)(q + (size_t)wh * NT * HD);
        const __half2* K2 = (const __half2*)(k + (size_t)wh * NT * HD);
        const __half2* V2 = (const __half2*)(v + (size_t)wh * NT * HD);
        for (int i = t; i < 784; i += 128) {           // 49 rows * 16 half2
            int r = i >> 4, cp = i & 15;
            ((__half2*)Qs)[r * 20 + cp] = Q2[i];
            ((__half2*)Ks)[r * 20 + cp] = K2[i];
            ((__half2*)Vs)[r * 20 + cp] = V2[i];
        }
        const __half2 z2 = __floats2half2_rn(0.f, 0.f);
        for (int i = t; i < 300; i += 128) {           // rows 49..63 (15*20)
            int r = 49 + i / 20, cp = i % 20;
            ((__half2*)Qs)[r * 20 + cp] = z2;
            ((__half2*)Ks)[r * 20 + cp] = z2;
            ((__half2*)Vs)[r * 20 + cp] = z2;
        }
        for (int i = t; i < 64 * 36; i += 128) ((__half2*)Ps)[i] = z2;
    }
    __syncthreads();

    const uint32_t qb = smem_u32(Qs), kb = smem_u32(Ks);
    const uint32_t vb = smem_u32(Vs), pb = smem_u32(Ps);

    // ---- S = Q K^T ----
    float s[8][4];
#pragma unroll
    for (int i = 0; i < 8; i++)
#pragma unroll
        for (int e = 0; e < 4; e++) s[i][e] = 0.f;

#pragma unroll
    for (int ks = 0; ks < 2; ks++) {
        uint32_t af[4];
        ldsm4(af, qb + (16 * warp + (lane & 15)) * 80 + (ks * 16 + (lane >> 4) * 8) * 2);
#pragma unroll
        for (int nt2 = 0; nt2 < 4; nt2++) {
            uint32_t bf[4];
            ldsm4(bf, kb + ((nt2 * 2 + (lane >> 4)) * 8 + (lane & 7)) * 80
                         + (ks * 16 + ((lane >> 3) & 1) * 8) * 2);
            mma_f16(s[nt2 * 2],     af, bf);
            mma_f16(s[nt2 * 2 + 1], af, bf + 2);
        }
    }

    // ---- bias + mask + store S ----
    {
        const int wi = (win >> 3) & 7, wj = win & 7;
#pragma unroll
        for (int nf = 0; nf < 8; nf++) {
#pragma unroll
            for (int e = 0; e < 4; e++) {
                int r = 16 * warp + g + (e >> 1) * 8;
                int c = nf * 8 + tg * 2 + (e & 1);
                if (r < NT && c < NT) {
                    int yr = r / WS, xr = r - yr * WS;
                    int yc = c / WS, xc = c - yc * WS;
                    float val = s[nf][e] +
                        rp[((yr - yc + WS - 1) * (2 * WS - 1) + (xr - xc + WS - 1)) * NH + head];
                    int hr = wi * WS + yr, wr_ = wj * WS + xr;
                    int hc = wi * WS + yc, wc_ = wj * WS + xc;
                    int ra = (hr < RB0 ? 0 : (hr < RB1 ? 1 : 2)) * 3 + (wr_ < RB0 ? 0 : (wr_ < RB1 ? 1 : 2));
                    int rb = (hc < RB0 ? 0 : (hc < RB1 ? 1 : 2)) * 3 + (wc_ < RB0 ? 0 : (wc_ < RB1 ? 1 : 2));
                    if (ra != rb) val -= 100.0f;
                    Ss[r * 64 + c] = val;
                }
            }
        }
    }
    __syncthreads();

    // ---- softmax (warp per row, rows strided by 4) -> P fp16 ----
    for (int r = warp; r < NT; r += 4) {
        float mx = -1e30f;
        for (int c = lane; c < NT; c += 32) mx = fmaxf(mx, Ss[r * 64 + c]);
#pragma unroll
        for (int off = 16; off; off >>= 1) mx = fmaxf(mx, __shfl_xor_sync(0xffffffffu, mx, off));
        float sum = 0.f;
        float e0 = 0.f, e1 = 0.f;
        {
            int c = lane;
            e0 = __expf(Ss[r * 64 + c] - mx); sum += e0;
            c += 32;
            if (c < NT) { e1 = __expf(Ss[r * 64 + c] - mx); sum += e1; }
        }
#pragma unroll
        for (int off = 16; off; off >>= 1) sum += __shfl_xor_sync(0xffffffffu, sum, off);
        float inv = 1.0f / sum;
        Ps[r * 72 + lane] = __float2half_rn(e0 * inv);
        if (lane + 32 < NT) Ps[r * 72 + lane + 32] = __float2half_rn(e1 * inv);
    }
    __syncthreads();

    // ---- O = P V ----
    float oa[4][4];
#pragma unroll
    for (int i = 0; i < 4; i++)
#pragma unroll
        for (int e = 0; e < 4; e++) oa[i][e] = 0.f;

#pragma unroll
    for (int ks = 0; ks < 4; ks++) {
        uint32_t af[4];
        ldsm4(af, pb + (16 * warp + (lane & 15)) * 144 + (ks * 16 + (lane >> 4) * 8) * 2);
        uint32_t b0[4], b1[4];
        ldsm4t(b0, vb + (ks * 16 + (lane & 15)) * 80 + ((lane >> 4) * 8) * 2);
        ldsm4t(b1, vb + (ks * 16 + (lane & 15)) * 80 + (16 + (lane >> 4) * 8) * 2);
        mma_f16(oa[0], af, b0);
        mma_f16(oa[1], af, b0 + 2);
        mma_f16(oa[2], af, b1);
        mma_f16(oa[3], af, b1 + 2);
    }

    // ---- store O (fp16, concat heads) ----
#pragma unroll
    for (int nf = 0; nf < 4; nf++) {
#pragma unroll
        for (int eh = 0; eh < 2; eh++) {
            int r = 16 * warp + g + eh * 8;
            if (r < NT) {
                int d = nf * 8 + tg * 2;
                __half2 hv = __floats2half2_rn(oa[nf][eh * 2], oa[nf][eh * 2 + 1]);
                *(__half2*)(o + ((size_t)win * NT + r) * C + head * HD + d) = hv;
            }
        }
    }
}

// ---------------------------------------------------------------------------
// Launch
// ---------------------------------------------------------------------------
extern "C" void kernel_launch(void* const* d_in, const int* in_sizes, int n_in,
                              void* d_out, int out_size)
{
    (void)in_sizes; (void)n_in; (void)out_size;
    const float* x     = (const float*)d_in[0];
    const float* n1w   = (const float*)d_in[1];
    const float* n1b   = (const float*)d_in[2];
    const float* qkv_w = (const float*)d_in[3];
    const float* qkv_b = (const float*)d_in[4];
    const float* rp    = (const float*)d_in[5];
    const float* out_w = (const float*)d_in[6];
    const float* out_b = (const float*)d_in[7];
    const float* n2w   = (const float*)d_in[8];
    const float* n2b   = (const float*)d_in[9];
    const float* fc1_w = (const float*)d_in[10];
    const float* fc1_b = (const float*)d_in[11];
    const float* fc2_w = (const float*)d_in[12];
    const float* fc2_b = (const float*)d_in[13];
    float* out = (float*)d_out;

    __half *xw, *o, *h1, *wt, *q, *k, *v;
    float *xres;
    cudaGetSymbolAddress((void**)&xw,   g_xw);
    cudaGetSymbolAddress((void**)&q,    g_q);
    cudaGetSymbolAddress((void**)&k,    g_k);
    cudaGetSymbolAddress((void**)&v,    g_v);
    cudaGetSymbolAddress((void**)&o,    g_o);
    cudaGetSymbolAddress((void**)&xres, g_xres);
    cudaGetSymbolAddress((void**)&h1,   g_h1);
    cudaGetSymbolAddress((void**)&wt,   g_wt);

    cudaFuncSetAttribute(gemm_f16<0, 512>,  cudaFuncAttributeMaxDynamicSharedMemorySize, SMEM_BYTES);
    cudaFuncSetAttribute(gemm_f16<1, 512>,  cudaFuncAttributeMaxDynamicSharedMemorySize, SMEM_BYTES);
    cudaFuncSetAttribute(gemm_f16<2, 512>,  cudaFuncAttributeMaxDynamicSharedMemorySize, SMEM_BYTES);
    cudaFuncSetAttribute(gemm_f16<3, 2048>, cudaFuncAttributeMaxDynamicSharedMemorySize, SMEM_BYTES);

    const int MT = M / BM;  // 392 m-tiles

    // 0. weights -> fp16
    cvt_h<<<(3 * C * C / 4 + 255) / 256, 256>>>((const float4*)qkv_w, (__half2*)(wt + W_QKV), 3 * C * C / 4);
    cvt_h<<<(C * C / 4 + 255) / 256, 256>>>((const float4*)out_w, (__half2*)(wt + W_OUT), C * C / 4);
    cvt_h<<<(4 * C * C / 4 + 255) / 256, 256>>>((const float4*)fc1_w, (__half2*)(wt + W_FC1), 4 * C * C / 4);
    cvt_h<<<(4 * C * C / 4 + 255) / 256, 256>>>((const float4*)fc2_w, (__half2*)(wt + W_FC2), 4 * C * C / 4);

    // 1. LN1 + shift + window partition  (fp16 out)
    ln_kernel<true><<<M, 256>>>(x, n1w, n1b, xw);
    // 2. qkv GEMM -> Q/K/V (head-major, fp16)
    gemm_f16<0, 512><<<dim3(12, MT), 256, SMEM_BYTES>>>(xw, wt + W_QKV, qkv_b, nullptr, q, k, v);
    // 3. windowed attention (tensor cores, fp16 out)
    attn_mma<<<GWIN * NH, 128>>>(q, k, v, rp, o);
    // 4. output projection + window reverse + unshift + residual (fp32)
    gemm_f16<1, 512><<<dim3(4, MT), 256, SMEM_BYTES>>>(o, wt + W_OUT, out_b, x, xres, nullptr, nullptr);
    // 5. LN2 (fp16 out)
    ln_kernel<false><<<M, 256>>>(xres, n2w, n2b, xw);
    // 6. fc1 + GELU (fp16 out)
    gemm_f16<2, 512><<<dim3(16, MT), 256, SMEM_BYTES>>>(xw, wt + W_FC1, fc1_b, nullptr, h1, nullptr, nullptr);
    // 7. fc2 + residual -> out (fp32)
    gemm_f16<3, 2048><<<dim3(4, MT), 256, SMEM_BYTES>>>(h1, wt + W_FC2, fc2_b, xres, out, nullptr, nullptr);
}